// round 6
// baseline (speedup 1.0000x reference)
#include <cuda_runtime.h>
#include <math.h>

#define N_NODES 16384
#define N_EDGES 524288
#define ET (N_EDGES + N_NODES)      // edges + self loops
#define HEADS 3
#define HID 64
#define IN_DIM 128
#define FEAT (HEADS * HID)          // 192
#define G4 (4 * HID)                // 256
#define NEG_SLOPE 0.2f
#define NODE_MASK (N_NODES - 1)     // N_NODES is 2^14

// ---------------- scratch (static device allocations; no cudaMalloc) ----------
__device__ float d_h[(size_t)N_NODES * FEAT];       // GAT transformed features
__device__ float d_asrc[N_NODES * HEADS];
__device__ float d_adst[N_NODES * HEADS];
__device__ float d_z[N_NODES * HEADS];              // softmax denominators
__device__ float d_p[(size_t)ET * HEADS];           // per-edge exp(e)
__device__ float d_gacc[(size_t)N_NODES * HID];     // aggregated messages (mean over heads)
__device__ float d_xg[(size_t)N_NODES * G4];        // precomputed input gates for LSTM
__device__ float d_hn[(size_t)N_NODES * HID];       // row-normalized h
__device__ int   d_is64;                            // edge_index dtype flag

// ---------------- edge dtype detection (int32 vs int64) -----------------------
// int64 little-endian with node ids < 16384 => every odd 32-bit word is zero.
// Sample only the first 16 words: in-bounds for BOTH dtypes.
__global__ void k_detect(const int* __restrict__ ei) {
    int is64 = 1;
#pragma unroll
    for (int k = 0; k < 8; k++)
        if (ei[2 * k + 1] != 0) is64 = 0;
    d_is64 = is64;
}

__device__ __forceinline__ void load_edge(const int* __restrict__ ei, int e, int is64,
                                          int& s, int& d) {
    if (e < N_EDGES) {
        if (is64) {
            const long long* e64 = (const long long*)ei;
            s = (int)e64[e];
            d = (int)e64[N_EDGES + e];
        } else {
            s = ei[e];
            d = ei[N_EDGES + e];
        }
        s &= NODE_MASK;   // never trap on bad data; wrong dtype shows as rel_err
        d &= NODE_MASK;
    } else {
        s = d = e - N_EDGES;
    }
}

// ---------------- init: zero the accumulators (must run every replay) ---------
__global__ void k_init() {
    for (int i = blockIdx.x * blockDim.x + threadIdx.x;
         i < N_NODES * HID; i += gridDim.x * blockDim.x) {
        if (i < N_NODES * HEADS) d_z[i] = 0.f;
        d_gacc[i] = 0.f;
    }
}

// ---------------- generic 64x64-tile NT GEMM: C = (A + abias) * B^T + cb1 + cb2
__device__ __forceinline__ void gemm_body(
    const float* __restrict__ A, int K,
    const float* __restrict__ B,
    float* __restrict__ C, int M,
    const float* __restrict__ abias,
    const float* __restrict__ cb1,
    const float* __restrict__ cb2)
{
    __shared__ float As[64][65];
    __shared__ float Bs[64][65];
    int tid = threadIdx.x;
    int tx = tid & 15;
    int ty = tid >> 4;
    int n0 = blockIdx.y * 64;
    int m0 = blockIdx.x * 64;

    float acc[4][4];
#pragma unroll
    for (int i = 0; i < 4; i++)
#pragma unroll
        for (int j = 0; j < 4; j++) acc[i][j] = 0.f;

    for (int k0 = 0; k0 < K; k0 += 64) {
#pragma unroll
        for (int i = 0; i < 16; i++) {
            int idx = tid + i * 256;
            int r = idx >> 6;
            int k = idx & 63;
            float av = A[(size_t)(n0 + r) * K + k0 + k];
            if (abias) av += abias[k0 + k];
            As[r][k] = av;
            Bs[r][k] = B[(size_t)(m0 + r) * K + k0 + k];
        }
        __syncthreads();
#pragma unroll
        for (int k = 0; k < 64; k++) {
            float a[4], b[4];
#pragma unroll
            for (int i = 0; i < 4; i++) {
                a[i] = As[ty * 4 + i][k];
                b[i] = Bs[tx * 4 + i][k];
            }
#pragma unroll
            for (int i = 0; i < 4; i++)
#pragma unroll
                for (int j = 0; j < 4; j++)
                    acc[i][j] = fmaf(a[i], b[j], acc[i][j]);
        }
        __syncthreads();
    }

#pragma unroll
    for (int i = 0; i < 4; i++)
#pragma unroll
        for (int j = 0; j < 4; j++) {
            int m = m0 + tx * 4 + j;
            float v = acc[i][j];
            if (cb1) v += cb1[m];
            if (cb2) v += cb2[m];
            C[(size_t)(n0 + ty * 4 + i) * M + m] = v;
        }
}

__global__ void k_gemm_h(const float* __restrict__ x, const float* __restrict__ lin_w) {
    gemm_body(x, IN_DIM, lin_w, d_h, FEAT, nullptr, nullptr, nullptr);
}

__global__ void k_gemm_xg(const float* __restrict__ w_ih, const float* __restrict__ gat_bias,
                          const float* __restrict__ b_ih, const float* __restrict__ b_hh) {
    gemm_body(d_gacc, HID, w_ih, d_xg, G4, gat_bias, b_ih, b_hh);
}

__global__ void k_corr(float* __restrict__ out_corr) {
    gemm_body(d_hn, HID, d_hn, out_corr, N_NODES, nullptr, nullptr, nullptr);
}

// ---------------- attention coefficients a_src, a_dst (warp per node) ---------
__global__ void k_attn(const float* __restrict__ att_src, const float* __restrict__ att_dst) {
    int warp = threadIdx.x >> 5;
    int lane = threadIdx.x & 31;
    int n = blockIdx.x * 8 + warp;
    if (n >= N_NODES) return;
    const float* hr = d_h + (size_t)n * FEAT;
#pragma unroll
    for (int hd = 0; hd < HEADS; hd++) {
        float h0 = hr[hd * 64 + lane];
        float h1 = hr[hd * 64 + 32 + lane];
        float s1 = h0 * att_src[hd * 64 + lane] + h1 * att_src[hd * 64 + 32 + lane];
        float s2 = h0 * att_dst[hd * 64 + lane] + h1 * att_dst[hd * 64 + 32 + lane];
#pragma unroll
        for (int o = 16; o; o >>= 1) {
            s1 += __shfl_xor_sync(0xffffffffu, s1, o);
            s2 += __shfl_xor_sync(0xffffffffu, s2, o);
        }
        if (lane == 0) {
            d_asrc[n * 3 + hd] = s1;
            d_adst[n * 3 + hd] = s2;
        }
    }
}

// ---------------- edge pass 1: p = exp(leakyrelu(e)), z accumulation ----------
// softmax shift is mathematically irrelevant to alpha; values are O(0.3), so m=0.
__global__ void k_edge_z(const int* __restrict__ ei) {
    int e = blockIdx.x * blockDim.x + threadIdx.x;
    if (e >= ET) return;
    int is64 = d_is64;
    int s, d;
    load_edge(ei, e, is64, s, d);
#pragma unroll
    for (int hd = 0; hd < 3; hd++) {
        float ev = d_asrc[s * 3 + hd] + d_adst[d * 3 + hd];
        ev = ev > 0.f ? ev : NEG_SLOPE * ev;
        float p = __expf(ev);
        d_p[(size_t)e * 3 + hd] = p;
        atomicAdd(&d_z[d * 3 + hd], p);
    }
}

// ---------------- edge pass 2: scatter messages (64 threads per edge) ---------
__global__ void k_edge_msg(const int* __restrict__ ei) {
    int le = threadIdx.x >> 6;
    int c = threadIdx.x & 63;
    int e = blockIdx.x * 4 + le;
    if (e >= ET) return;
    int is64 = d_is64;
    int s, d;
    load_edge(ei, e, is64, s, d);
    float a0 = d_p[(size_t)e * 3 + 0] / d_z[d * 3 + 0];
    float a1 = d_p[(size_t)e * 3 + 1] / d_z[d * 3 + 1];
    float a2 = d_p[(size_t)e * 3 + 2] / d_z[d * 3 + 2];
    const float* hr = d_h + (size_t)s * FEAT;
    float msg = (hr[c] * a0 + hr[64 + c] * a1 + hr[128 + c] * a2) * (1.f / 3.f);
    atomicAdd(&d_gacc[(size_t)d * 64 + c], msg);
}

// ---------------- LSTM: single block, 256 threads, w_hh rows in registers -----
__global__ void __launch_bounds__(256, 1) k_lstm(const float* __restrict__ w_hh,
                                                 float* __restrict__ out_h) {
    __shared__ __align__(16) float h_s[64];
    __shared__ float gate_s[256];
    int t = threadIdx.x;

    float w[64];
#pragma unroll
    for (int k = 0; k < 64; k++) w[k] = w_hh[t * 64 + k];

    float c = 0.f;
    if (t < 64) h_s[t] = 0.f;
    __syncthreads();

    float xg_cur = d_xg[t];
    for (int step = 0; step < N_NODES; step++) {
        float xg_nxt = (step < N_NODES - 1) ? __ldg(&d_xg[(size_t)(step + 1) * G4 + t]) : 0.f;

        float a0 = 0.f, a1 = 0.f, a2 = 0.f, a3 = 0.f;
        const float4* h4 = (const float4*)h_s;
#pragma unroll
        for (int k = 0; k < 16; k++) {
            float4 hv = h4[k];
            a0 = fmaf(w[4 * k + 0], hv.x, a0);
            a1 = fmaf(w[4 * k + 1], hv.y, a1);
            a2 = fmaf(w[4 * k + 2], hv.z, a2);
            a3 = fmaf(w[4 * k + 3], hv.w, a3);
        }
        float acc = xg_cur + ((a0 + a1) + (a2 + a3));

        float act;
        if (t < 128 || t >= 192) {
            act = 1.f / (1.f + __expf(-acc));          // i, f, o: sigmoid
        } else {
            float e2 = __expf(2.f * acc);              // g: tanh
            act = 1.f - 2.f / (e2 + 1.f);
        }
        gate_s[t] = act;
        __syncthreads();

        if (t < 64) {
            float iv = gate_s[t];
            float fv = gate_s[64 + t];
            float gv = gate_s[128 + t];
            float ov = gate_s[192 + t];
            c = fv * c + iv * gv;
            float e2 = __expf(2.f * c);
            float th = 1.f - 2.f / (e2 + 1.f);
            float hv = ov * th;
            h_s[t] = hv;
            out_h[(size_t)step * HID + t] = hv;
        }
        __syncthreads();
        xg_cur = xg_nxt;
    }
}

// ---------------- row normalization ------------------------------------------
__global__ void k_norm(const float* __restrict__ out_h) {
    int warp = threadIdx.x >> 5;
    int lane = threadIdx.x & 31;
    int n = blockIdx.x * 8 + warp;
    if (n >= N_NODES) return;
    float v0 = out_h[(size_t)n * 64 + lane];
    float v1 = out_h[(size_t)n * 64 + 32 + lane];
    float ss = v0 * v0 + v1 * v1;
#pragma unroll
    for (int o = 16; o; o >>= 1) ss += __shfl_xor_sync(0xffffffffu, ss, o);
    float nrm = fmaxf(sqrtf(ss), 1e-12f);
    float inv = 1.f / nrm;
    d_hn[(size_t)n * 64 + lane] = v0 * inv;
    d_hn[(size_t)n * 64 + 32 + lane] = v1 * inv;
}

// ---------------- uncertainty MLP heads (warp per node) -----------------------
__global__ void k_mlp(const float* __restrict__ out_h,
                      const float* __restrict__ w1, const float* __restrict__ b1,
                      const float* __restrict__ w2, const float* __restrict__ b2,
                      float* __restrict__ mu, float* __restrict__ sigma) {
    int warp = threadIdx.x >> 5;
    int lane = threadIdx.x & 31;
    int n = blockIdx.x * 8 + warp;
    if (n >= N_NODES) return;
    const float* hr = out_h + (size_t)n * 64;
    float acc = b1[lane];
#pragma unroll
    for (int k = 0; k < 64; k++) acc = fmaf(hr[k], w1[lane * 64 + k], acc);
    acc = fmaxf(acc, 0.f);
    float m0 = acc * w2[lane];
    float m1 = acc * w2[32 + lane];
#pragma unroll
    for (int o = 16; o; o >>= 1) {
        m0 += __shfl_xor_sync(0xffffffffu, m0, o);
        m1 += __shfl_xor_sync(0xffffffffu, m1, o);
    }
    if (lane == 0) {
        mu[n] = m0 + b2[0];
        sigma[n] = m1 + b2[1];
    }
}

// ---------------- launcher ----------------------------------------------------
extern "C" void kernel_launch(void* const* d_in, const int* in_sizes, int n_in,
                              void* d_out, int out_size) {
    const float* x        = (const float*)d_in[0];
    const int*   ei       = (const int*)d_in[1];     // int32 or int64; detected on device
    const float* lin_w    = (const float*)d_in[2];
    const float* att_src  = (const float*)d_in[3];
    const float* att_dst  = (const float*)d_in[4];
    const float* gat_bias = (const float*)d_in[5];
    const float* w_ih     = (const float*)d_in[6];
    const float* w_hh     = (const float*)d_in[7];
    const float* b_ih     = (const float*)d_in[8];
    const float* b_hh     = (const float*)d_in[9];
    const float* u_w1     = (const float*)d_in[10];
    const float* u_b1     = (const float*)d_in[11];
    const float* u_w2     = (const float*)d_in[12];
    const float* u_b2     = (const float*)d_in[13];

    float* out       = (float*)d_out;
    float* out_h     = out;                                   // 16384*64
    float* out_corr  = out + (size_t)N_NODES * HID;           // 16384*16384
    float* out_mu    = out_corr + (size_t)N_NODES * N_NODES;  // 16384
    float* out_sigma = out_mu + N_NODES;                      // 16384

    (void)in_sizes; (void)n_in; (void)out_size;

    // 0. detect edge_index dtype (int32 vs int64)
    k_detect<<<1, 1>>>(ei);

    // 1. zero accumulators
    k_init<<<512, 256>>>();

    // 2. h = x @ lin_w^T   (16384x128 @ 128x192)
    k_gemm_h<<<dim3(FEAT / 64, N_NODES / 64), 256>>>(x, lin_w);

    // 3. attention coefficients
    k_attn<<<N_NODES / 8, 256>>>(att_src, att_dst);

    // 4. edge softmax denominators (segment-max shift skipped: alpha-invariant)
    k_edge_z<<<(ET + 255) / 256, 256>>>(ei);

    // 5. message scatter (mean over heads folded in)
    k_edge_msg<<<(ET + 3) / 4, 256>>>(ei);

    // 6. xg = (gacc + gat_bias) @ w_ih^T + b_ih + b_hh
    k_gemm_xg<<<dim3(G4 / 64, N_NODES / 64), 256>>>(w_ih, gat_bias, b_ih, b_hh);

    // 7. sequential LSTM over 16384 steps (writes h directly to output)
    k_lstm<<<1, 256>>>(w_hh, out_h);

    // 8. row-normalize h
    k_norm<<<N_NODES / 8, 256>>>(out_h);

    // 9. corr = hn @ hn^T  (16384x16384)
    k_corr<<<dim3(N_NODES / 64, N_NODES / 64), 256>>>(out_corr);

    // 10. mu / sigma heads
    k_mlp<<<N_NODES / 8, 256>>>(out_h, u_w1, u_b1, u_w2, u_b2, out_mu, out_sigma);
}

// round 7
// speedup vs baseline: 1.0328x; 1.0328x over previous
#include <cuda_runtime.h>
#include <math.h>
#include <stdint.h>

#define N_NODES 16384
#define N_EDGES 524288
#define ET (N_EDGES + N_NODES)      // edges + self loops
#define HEADS 3
#define HID 64
#define IN_DIM 128
#define FEAT (HEADS * HID)          // 192
#define G4 (4 * HID)                // 256
#define NEG_SLOPE 0.2f
#define NODE_MASK (N_NODES - 1)     // N_NODES is 2^14

// ---------------- scratch (static device allocations; no cudaMalloc) ----------
__device__ float d_h[(size_t)N_NODES * FEAT];       // GAT transformed features
__device__ float d_asrc[N_NODES * HEADS];
__device__ float d_adst[N_NODES * HEADS];
__device__ float d_z[N_NODES * HEADS];              // softmax denominators
__device__ float d_p[(size_t)ET * HEADS];           // per-edge exp(e)
__device__ float d_gacc[(size_t)N_NODES * HID];     // aggregated messages (mean over heads)
__device__ float d_xg[(size_t)N_NODES * G4];        // precomputed input gates for LSTM
__device__ float d_hn[(size_t)N_NODES * HID];       // row-normalized h
__device__ int   d_is64;                            // edge_index dtype flag

// ---------------- edge dtype detection (int32 vs int64) -----------------------
__global__ void k_detect(const int* __restrict__ ei) {
    int is64 = 1;
#pragma unroll
    for (int k = 0; k < 8; k++)
        if (ei[2 * k + 1] != 0) is64 = 0;
    d_is64 = is64;
}

__device__ __forceinline__ void load_edge(const int* __restrict__ ei, int e, int is64,
                                          int& s, int& d) {
    if (e < N_EDGES) {
        if (is64) {
            const long long* e64 = (const long long*)ei;
            s = (int)e64[e];
            d = (int)e64[N_EDGES + e];
        } else {
            s = ei[e];
            d = ei[N_EDGES + e];
        }
        s &= NODE_MASK;
        d &= NODE_MASK;
    } else {
        s = d = e - N_EDGES;
    }
}

// ---------------- init: zero the accumulators (must run every replay) ---------
__global__ void k_init() {
    for (int i = blockIdx.x * blockDim.x + threadIdx.x;
         i < N_NODES * HID; i += gridDim.x * blockDim.x) {
        if (i < N_NODES * HEADS) d_z[i] = 0.f;
        d_gacc[i] = 0.f;
    }
}

// ---------------- generic 64x64-tile NT GEMM: C = (A + abias) * B^T + cb1 + cb2
__device__ __forceinline__ void gemm_body(
    const float* __restrict__ A, int K,
    const float* __restrict__ B,
    float* __restrict__ C, int M,
    const float* __restrict__ abias,
    const float* __restrict__ cb1,
    const float* __restrict__ cb2)
{
    __shared__ float As[64][65];
    __shared__ float Bs[64][65];
    int tid = threadIdx.x;
    int tx = tid & 15;
    int ty = tid >> 4;
    int n0 = blockIdx.y * 64;
    int m0 = blockIdx.x * 64;

    float acc[4][4];
#pragma unroll
    for (int i = 0; i < 4; i++)
#pragma unroll
        for (int j = 0; j < 4; j++) acc[i][j] = 0.f;

    for (int k0 = 0; k0 < K; k0 += 64) {
#pragma unroll
        for (int i = 0; i < 16; i++) {
            int idx = tid + i * 256;
            int r = idx >> 6;
            int k = idx & 63;
            float av = A[(size_t)(n0 + r) * K + k0 + k];
            if (abias) av += abias[k0 + k];
            As[r][k] = av;
            Bs[r][k] = B[(size_t)(m0 + r) * K + k0 + k];
        }
        __syncthreads();
#pragma unroll
        for (int k = 0; k < 64; k++) {
            float a[4], b[4];
#pragma unroll
            for (int i = 0; i < 4; i++) {
                a[i] = As[ty * 4 + i][k];
                b[i] = Bs[tx * 4 + i][k];
            }
#pragma unroll
            for (int i = 0; i < 4; i++)
#pragma unroll
                for (int j = 0; j < 4; j++)
                    acc[i][j] = fmaf(a[i], b[j], acc[i][j]);
        }
        __syncthreads();
    }

#pragma unroll
    for (int i = 0; i < 4; i++)
#pragma unroll
        for (int j = 0; j < 4; j++) {
            int m = m0 + tx * 4 + j;
            float v = acc[i][j];
            if (cb1) v += cb1[m];
            if (cb2) v += cb2[m];
            C[(size_t)(n0 + ty * 4 + i) * M + m] = v;
        }
}

__global__ void k_gemm_h(const float* __restrict__ x, const float* __restrict__ lin_w) {
    gemm_body(x, IN_DIM, lin_w, d_h, FEAT, nullptr, nullptr, nullptr);
}

__global__ void k_gemm_xg(const float* __restrict__ w_ih, const float* __restrict__ gat_bias,
                          const float* __restrict__ b_ih, const float* __restrict__ b_hh) {
    gemm_body(d_gacc, HID, w_ih, d_xg, G4, gat_bias, b_ih, b_hh);
}

// ---------------- corr: symmetric NT GEMM, upper-triangular tiles only --------
// C = hn @ hn^T. For tile (bx >= by): compute, write direct; if off-diagonal,
// also write the transposed tile (staged through smem, conflict-free, coalesced).
__global__ void k_corr_sym(float* __restrict__ C) {
    int bx = blockIdx.x, by = blockIdx.y;
    if (bx < by) return;

    __shared__ float As[64][65];
    __shared__ float Bs[64][65];
    int tid = threadIdx.x;
    int tx = tid & 15;
    int ty = tid >> 4;
    int n0 = by * 64;        // row tile
    int m0 = bx * 64;        // col tile
    const float* A = d_hn;

    float acc[4][4];
#pragma unroll
    for (int i = 0; i < 4; i++)
#pragma unroll
        for (int j = 0; j < 4; j++) acc[i][j] = 0.f;

    // K = HID = 64: single k-tile
#pragma unroll
    for (int i = 0; i < 16; i++) {
        int idx = tid + i * 256;
        int r = idx >> 6;
        int k = idx & 63;
        As[r][k] = A[(size_t)(n0 + r) * HID + k];
        Bs[r][k] = A[(size_t)(m0 + r) * HID + k];
    }
    __syncthreads();
#pragma unroll
    for (int k = 0; k < 64; k++) {
        float a[4], b[4];
#pragma unroll
        for (int i = 0; i < 4; i++) {
            a[i] = As[ty * 4 + i][k];
            b[i] = Bs[tx * 4 + i][k];
        }
#pragma unroll
        for (int i = 0; i < 4; i++)
#pragma unroll
            for (int j = 0; j < 4; j++)
                acc[i][j] = fmaf(a[i], b[j], acc[i][j]);
    }

    // direct tile write: C[n0+r][m0+c]
#pragma unroll
    for (int i = 0; i < 4; i++)
#pragma unroll
        for (int j = 0; j < 4; j++)
            C[(size_t)(n0 + ty * 4 + i) * N_NODES + m0 + tx * 4 + j] = acc[i][j];

    if (bx == by) return;

    // mirror tile: stage acc into As, then write C[m0+row][n0+col] = As[col][row]
    __syncthreads();
#pragma unroll
    for (int i = 0; i < 4; i++)
#pragma unroll
        for (int j = 0; j < 4; j++)
            As[ty * 4 + i][tx * 4 + j] = acc[i][j];
    __syncthreads();
    int col = tid & 63;
    int r0 = tid >> 6;
#pragma unroll
    for (int i = 0; i < 16; i++) {
        int row = i * 4 + r0;
        C[(size_t)(m0 + row) * N_NODES + n0 + col] = As[col][row];
    }
}

// ---------------- attention coefficients a_src, a_dst (warp per node) ---------
__global__ void k_attn(const float* __restrict__ att_src, const float* __restrict__ att_dst) {
    int warp = threadIdx.x >> 5;
    int lane = threadIdx.x & 31;
    int n = blockIdx.x * 8 + warp;
    if (n >= N_NODES) return;
    const float* hr = d_h + (size_t)n * FEAT;
#pragma unroll
    for (int hd = 0; hd < HEADS; hd++) {
        float h0 = hr[hd * 64 + lane];
        float h1 = hr[hd * 64 + 32 + lane];
        float s1 = h0 * att_src[hd * 64 + lane] + h1 * att_src[hd * 64 + 32 + lane];
        float s2 = h0 * att_dst[hd * 64 + lane] + h1 * att_dst[hd * 64 + 32 + lane];
#pragma unroll
        for (int o = 16; o; o >>= 1) {
            s1 += __shfl_xor_sync(0xffffffffu, s1, o);
            s2 += __shfl_xor_sync(0xffffffffu, s2, o);
        }
        if (lane == 0) {
            d_asrc[n * 3 + hd] = s1;
            d_adst[n * 3 + hd] = s2;
        }
    }
}

// ---------------- edge pass 1: p = exp(leakyrelu(e)), z accumulation ----------
__global__ void k_edge_z(const int* __restrict__ ei) {
    int e = blockIdx.x * blockDim.x + threadIdx.x;
    if (e >= ET) return;
    int is64 = d_is64;
    int s, d;
    load_edge(ei, e, is64, s, d);
#pragma unroll
    for (int hd = 0; hd < 3; hd++) {
        float ev = d_asrc[s * 3 + hd] + d_adst[d * 3 + hd];
        ev = ev > 0.f ? ev : NEG_SLOPE * ev;
        float p = __expf(ev);
        d_p[(size_t)e * 3 + hd] = p;
        atomicAdd(&d_z[d * 3 + hd], p);
    }
}

// ---------------- edge pass 2: scatter messages (64 threads per edge) ---------
__global__ void k_edge_msg(const int* __restrict__ ei) {
    int le = threadIdx.x >> 6;
    int c = threadIdx.x & 63;
    int e = blockIdx.x * 4 + le;
    if (e >= ET) return;
    int is64 = d_is64;
    int s, d;
    load_edge(ei, e, is64, s, d);
    float a0 = d_p[(size_t)e * 3 + 0] / d_z[d * 3 + 0];
    float a1 = d_p[(size_t)e * 3 + 1] / d_z[d * 3 + 1];
    float a2 = d_p[(size_t)e * 3 + 2] / d_z[d * 3 + 2];
    const float* hr = d_h + (size_t)s * FEAT;
    float msg = (hr[c] * a0 + hr[64 + c] * a1 + hr[128 + c] * a2) * (1.f / 3.f);
    atomicAdd(&d_gacc[(size_t)d * 64 + c], msg);
}

// ---------------- LSTM: single block, 256 threads ----------------------------
// f32x2 packed FMA matvec (8 accumulator chains) + depth-3 xg prefetch ring
// to cover DRAM latency (~600cyc > step time).
__global__ void __launch_bounds__(256, 1) k_lstm(const float* __restrict__ w_hh,
                                                 float* __restrict__ out_h) {
    __shared__ __align__(16) float h_s[64];
    __shared__ float gate_s[256];
    int t = threadIdx.x;

    // packed weights: w2[k] = (w[2k], w[2k+1])
    unsigned long long w2[32];
    {
        const float* wrow = w_hh + (size_t)t * 64;
#pragma unroll
        for (int k = 0; k < 32; k++) {
            asm("mov.b64 %0, {%1, %2};"
                : "=l"(w2[k]) : "f"(wrow[2 * k]), "f"(wrow[2 * k + 1]));
        }
    }

    float c = 0.f;
    if (t < 64) h_s[t] = 0.f;
    __syncthreads();

    // prefetch ring, depth 3
    float xgA = d_xg[t];
    float xgB = d_xg[G4 + t];
    float xgC = d_xg[2 * G4 + t];

    for (int step = 0; step < N_NODES; step++) {
        float xgD = (step + 3 < N_NODES) ? __ldg(&d_xg[(size_t)(step + 3) * G4 + t]) : 0.f;

        unsigned long long a[8];
#pragma unroll
        for (int i = 0; i < 8; i++) a[i] = 0ull;

        const float4* h4 = (const float4*)h_s;
#pragma unroll
        for (int k = 0; k < 16; k++) {
            float4 hv = h4[k];
            unsigned long long hlo, hhi;
            asm("mov.b64 %0, {%1, %2};" : "=l"(hlo) : "f"(hv.x), "f"(hv.y));
            asm("mov.b64 %0, {%1, %2};" : "=l"(hhi) : "f"(hv.z), "f"(hv.w));
            asm("fma.rn.f32x2 %0, %1, %2, %0;"
                : "+l"(a[(2 * k) & 7]) : "l"(w2[2 * k]), "l"(hlo));
            asm("fma.rn.f32x2 %0, %1, %2, %0;"
                : "+l"(a[(2 * k + 1) & 7]) : "l"(w2[2 * k + 1]), "l"(hhi));
        }
        // pairwise reduce 8 chains
        asm("add.rn.f32x2 %0, %0, %1;" : "+l"(a[0]) : "l"(a[4]));
        asm("add.rn.f32x2 %0, %0, %1;" : "+l"(a[1]) : "l"(a[5]));
        asm("add.rn.f32x2 %0, %0, %1;" : "+l"(a[2]) : "l"(a[6]));
        asm("add.rn.f32x2 %0, %0, %1;" : "+l"(a[3]) : "l"(a[7]));
        asm("add.rn.f32x2 %0, %0, %1;" : "+l"(a[0]) : "l"(a[2]));
        asm("add.rn.f32x2 %0, %0, %1;" : "+l"(a[1]) : "l"(a[3]));
        asm("add.rn.f32x2 %0, %0, %1;" : "+l"(a[0]) : "l"(a[1]));
        float s0, s1;
        asm("mov.b64 {%0, %1}, %2;" : "=f"(s0), "=f"(s1) : "l"(a[0]));
        float acc = xgA + (s0 + s1);

        float act;
        if (t < 128 || t >= 192) {
            act = 1.f / (1.f + __expf(-acc));          // i, f, o: sigmoid
        } else {
            float e2 = __expf(2.f * acc);              // g: tanh
            act = 1.f - 2.f / (e2 + 1.f);
        }
        gate_s[t] = act;
        __syncthreads();

        if (t < 64) {
            float iv = gate_s[t];
            float fv = gate_s[64 + t];
            float gv = gate_s[128 + t];
            float ov = gate_s[192 + t];
            c = fv * c + iv * gv;
            float e2 = __expf(2.f * c);
            float th = 1.f - 2.f / (e2 + 1.f);
            float hv = ov * th;
            h_s[t] = hv;
            out_h[(size_t)step * HID + t] = hv;
        }
        __syncthreads();

        xgA = xgB; xgB = xgC; xgC = xgD;
    }
}

// ---------------- row normalization ------------------------------------------
__global__ void k_norm(const float* __restrict__ out_h) {
    int warp = threadIdx.x >> 5;
    int lane = threadIdx.x & 31;
    int n = blockIdx.x * 8 + warp;
    if (n >= N_NODES) return;
    float v0 = out_h[(size_t)n * 64 + lane];
    float v1 = out_h[(size_t)n * 64 + 32 + lane];
    float ss = v0 * v0 + v1 * v1;
#pragma unroll
    for (int o = 16; o; o >>= 1) ss += __shfl_xor_sync(0xffffffffu, ss, o);
    float nrm = fmaxf(sqrtf(ss), 1e-12f);
    float inv = 1.f / nrm;
    d_hn[(size_t)n * 64 + lane] = v0 * inv;
    d_hn[(size_t)n * 64 + 32 + lane] = v1 * inv;
}

// ---------------- uncertainty MLP heads (warp per node) -----------------------
__global__ void k_mlp(const float* __restrict__ out_h,
                      const float* __restrict__ w1, const float* __restrict__ b1,
                      const float* __restrict__ w2, const float* __restrict__ b2,
                      float* __restrict__ mu, float* __restrict__ sigma) {
    int warp = threadIdx.x >> 5;
    int lane = threadIdx.x & 31;
    int n = blockIdx.x * 8 + warp;
    if (n >= N_NODES) return;
    const float* hr = out_h + (size_t)n * 64;
    float acc = b1[lane];
#pragma unroll
    for (int k = 0; k < 64; k++) acc = fmaf(hr[k], w1[lane * 64 + k], acc);
    acc = fmaxf(acc, 0.f);
    float m0 = acc * w2[lane];
    float m1 = acc * w2[32 + lane];
#pragma unroll
    for (int o = 16; o; o >>= 1) {
        m0 += __shfl_xor_sync(0xffffffffu, m0, o);
        m1 += __shfl_xor_sync(0xffffffffu, m1, o);
    }
    if (lane == 0) {
        mu[n] = m0 + b2[0];
        sigma[n] = m1 + b2[1];
    }
}

// ---------------- launcher ----------------------------------------------------
extern "C" void kernel_launch(void* const* d_in, const int* in_sizes, int n_in,
                              void* d_out, int out_size) {
    const float* x        = (const float*)d_in[0];
    const int*   ei       = (const int*)d_in[1];
    const float* lin_w    = (const float*)d_in[2];
    const float* att_src  = (const float*)d_in[3];
    const float* att_dst  = (const float*)d_in[4];
    const float* gat_bias = (const float*)d_in[5];
    const float* w_ih     = (const float*)d_in[6];
    const float* w_hh     = (const float*)d_in[7];
    const float* b_ih     = (const float*)d_in[8];
    const float* b_hh     = (const float*)d_in[9];
    const float* u_w1     = (const float*)d_in[10];
    const float* u_b1     = (const float*)d_in[11];
    const float* u_w2     = (const float*)d_in[12];
    const float* u_b2     = (const float*)d_in[13];

    float* out       = (float*)d_out;
    float* out_h     = out;                                   // 16384*64
    float* out_corr  = out + (size_t)N_NODES * HID;           // 16384*16384
    float* out_mu    = out_corr + (size_t)N_NODES * N_NODES;  // 16384
    float* out_sigma = out_mu + N_NODES;                      // 16384

    (void)in_sizes; (void)n_in; (void)out_size;

    k_detect<<<1, 1>>>(ei);
    k_init<<<512, 256>>>();
    k_gemm_h<<<dim3(FEAT / 64, N_NODES / 64), 256>>>(x, lin_w);
    k_attn<<<N_NODES / 8, 256>>>(att_src, att_dst);
    k_edge_z<<<(ET + 255) / 256, 256>>>(ei);
    k_edge_msg<<<(ET + 3) / 4, 256>>>(ei);
    k_gemm_xg<<<dim3(G4 / 64, N_NODES / 64), 256>>>(w_ih, gat_bias, b_ih, b_hh);
    k_lstm<<<1, 256>>>(w_hh, out_h);
    k_norm<<<N_NODES / 8, 256>>>(out_h);
    k_corr_sym<<<dim3(N_NODES / 64, N_NODES / 64), 256>>>(out_corr);
    k_mlp<<<N_NODES / 8, 256>>>(out_h, u_w1, u_b1, u_w2, u_b2, out_mu, out_sigma);
}